// round 1
// baseline (speedup 1.0000x reference)
#include <cuda_runtime.h>
#include <cstdint>

// Problem constants (shapes are fixed by the dataset)
#define B_    2048
#define F_    512
#define H_    64
#define K_    8
#define D_    128
#define ASR_  128
#define MM_   768
#define OUT_  256
#define ZPRE_ (ASR_ + MM_)          // 896
#define ZK_   (ZPRE_ + F_ * K_)     // 4992 (virtual contraction dim)
#define KHALF (ZK_ / 2)             // 2496 (split-K)
#define PROJ_IN_ (ASR_ + MM_ + F_ * D_)   // 66432

typedef unsigned long long ull;

// ---------- packed f32x2 helpers (Blackwell FFMA2) ----------
__device__ __forceinline__ ull pack2(float lo, float hi) {
    ull r; asm("mov.b64 %0, {%1, %2};" : "=l"(r) : "f"(lo), "f"(hi)); return r;
}
__device__ __forceinline__ void unpack2(ull v, float& lo, float& hi) {
    asm("mov.b64 {%0, %1}, %2;" : "=f"(lo), "=f"(hi) : "l"(v));
}
__device__ __forceinline__ void ffma2(ull& c, ull a, ull b) {
    asm("fma.rn.f32x2 %0, %1, %2, %0;" : "+l"(c) : "l"(a), "l"(b));
}

// ---------- device scratch (no allocation allowed) ----------
__device__ float g_P[(size_t)B_ * (F_ * K_)];       // 2048 x 4096   (32 MB)
__device__ float g_Bmat[(size_t)ZK_ * OUT_];        // 4992 x 256    (5 MB)
__device__ float g_CP[2 * (size_t)B_ * OUT_];       // split-K partials (4 MB)

// ============================================================
// Kernel A: sanitize + per-feature MLP + leaky + softmax -> P
// grid = F_ blocks, 256 threads; each thread handles 8 batch rows.
// ============================================================
__global__ __launch_bounds__(256) void kernelA(
    const float* __restrict__ stat, const float* __restrict__ w1,
    const float* __restrict__ b1,   const float* __restrict__ w2,
    const float* __restrict__ b2,   const float* __restrict__ tau)
{
    __shared__ float w1s[H_], b1s[H_], b2s[K_], taus[K_];
    __shared__ ull   w2s[H_ * K_ / 2];    // [64][8] floats viewed as [64][4] f32x2

    const int f = blockIdx.x;
    const int tid = threadIdx.x;

    if (tid < H_) {
        const float* p = w1 + (size_t)f * 3 * H_;
        w1s[tid] = p[tid] + p[H_ + tid] + p[2 * H_ + tid];   // sum over 3 identical copies
        b1s[tid] = b1[(size_t)f * H_ + tid];
    } else if (tid < H_ + K_) {
        b2s[tid - H_] = b2[(size_t)f * K_ + tid - H_];
        taus[tid - H_] = tau[(size_t)f * K_ + tid - H_];
    }
    if (tid < 128) ((float4*)w2s)[tid] = ((const float4*)(w2 + (size_t)f * H_ * K_))[tid];
    __syncthreads();

    float x[8];
#pragma unroll
    for (int i = 0; i < 8; i++) {
        float v = stat[(size_t)(i * 256 + tid) * F_ + f];
        x[i] = (v >= 0.f) ? v : 0.f;           // NaN and negatives -> 0
    }

    ull acc[8][4];
#pragma unroll
    for (int i = 0; i < 8; i++)
#pragma unroll
        for (int k = 0; k < 4; k++) acc[i][k] = 0ull;

#pragma unroll 4
    for (int j = 0; j < H_; j++) {
        const float wj = w1s[j];
        const float bj = b1s[j];
        const ull u0 = w2s[j * 4 + 0];
        const ull u1 = w2s[j * 4 + 1];
        const ull u2 = w2s[j * 4 + 2];
        const ull u3 = w2s[j * 4 + 3];
#pragma unroll
        for (int i = 0; i < 8; i++) {
            float h = fmaf(x[i], wj, bj);
            h = fmaxf(h, 0.01f * h);           // leaky relu
            ull h2 = pack2(h, h);
            ffma2(acc[i][0], h2, u0);
            ffma2(acc[i][1], h2, u1);
            ffma2(acc[i][2], h2, u2);
            ffma2(acc[i][3], h2, u3);
        }
    }

#pragma unroll
    for (int i = 0; i < 8; i++) {
        float s[8];
#pragma unroll
        for (int k = 0; k < 4; k++) unpack2(acc[i][k], s[2 * k], s[2 * k + 1]);
        float mx = -3.0e38f;
#pragma unroll
        for (int k = 0; k < K_; k++) {
            float pre = s[k] + b2s[k];
            pre = fmaxf(pre, 0.01f * pre);     // leaky relu
            pre *= taus[k];                    // tau scale
            s[k] = pre;
            mx = fmaxf(mx, pre);
        }
        float sum = 0.f;
#pragma unroll
        for (int k = 0; k < K_; k++) { s[k] = __expf(s[k] - mx); sum += s[k]; }
        const float inv = __frcp_rn(sum);
        float4 o0 = make_float4(s[0] * inv, s[1] * inv, s[2] * inv, s[3] * inv);
        float4 o1 = make_float4(s[4] * inv, s[5] * inv, s[6] * inv, s[7] * inv);
        float4* dst = (float4*)(g_P + (size_t)(i * 256 + tid) * (F_ * K_) + f * K_);
        dst[0] = o0; dst[1] = o1;
    }
}

// ============================================================
// Kernel B: build Bmat[4992][256].
//   rows 0..895:   W^T  (Bmat[i][o] = proj_w[o][i])
//   rows 896..:    M[f*8+k][o] = sum_d emb[f,k,d] * proj_w[o, 896+f*128+d]
// grid = 512 + 28 blocks, 256 threads.
// ============================================================
__global__ __launch_bounds__(256) void kernelB(
    const float* __restrict__ emb, const float* __restrict__ pw)
{
    const int blk = blockIdx.x;
    const int tid = threadIdx.x;
    if (blk < F_) {
        __shared__ float es[K_][D_];           // 4 KB
        const int f = blk;
        ((float4*)es)[tid] = ((const float4*)(emb + (size_t)f * K_ * D_))[tid];
        __syncthreads();
        const int w = tid >> 5, l = tid & 31;
        const float* base = pw + ZPRE_ + (size_t)f * D_;
        for (int oi = 0; oi < 32; oi++) {
            const int o = w * 32 + oi;
            float4 wv = *(const float4*)(base + (size_t)o * PROJ_IN_ + l * 4);
            float acc[K_];
#pragma unroll
            for (int k = 0; k < K_; k++) {
                float4 e4 = *(const float4*)&es[k][l * 4];
                acc[k] = wv.x * e4.x + wv.y * e4.y + wv.z * e4.z + wv.w * e4.w;
            }
#pragma unroll
            for (int off = 16; off > 0; off >>= 1)
#pragma unroll
                for (int k = 0; k < K_; k++)
                    acc[k] += __shfl_xor_sync(0xffffffff, acc[k], off);
            if (l == 0) {
#pragma unroll
                for (int k = 0; k < K_; k++)
                    g_Bmat[(size_t)(ZPRE_ + f * K_ + k) * OUT_ + o] = acc[k];
            }
        }
    } else {
        // transpose W[:, 0:896] into Bmat[0:896][:]
        const int i0 = (blk - F_) * 32;        // 28 blocks * 32 = 896
        const int o = tid;
        for (int ii = 0; ii < 32; ii++)
            g_Bmat[(size_t)(i0 + ii) * OUT_ + o] = pw[(size_t)o * PROJ_IN_ + i0 + ii];
    }
}

// ============================================================
// Kernel C: split-K SGEMM.  CP[z] += Z[2048 x 2496] @ Bmat-half
// Z is virtual: [asr | mm | P].  BM=64 BN=64 BK=16, 128 threads,
// thread tile 8(m) x 4(n) with f32x2 accumulators (m-paired).
// grid = (32, 4, 2)
// ============================================================
__global__ __launch_bounds__(128) void kernelC(
    const float* __restrict__ asr, const float* __restrict__ mmv)
{
    __shared__ float As[16][64];
    __shared__ float Bs[16][64];

    const int tid = threadIdx.x;
    const int gm = blockIdx.x * 64;
    const int gn = blockIdx.y * 64;
    const int kbase = blockIdx.z * KHALF;
    const int m0 = (tid >> 4) * 8;
    const int n0 = (tid & 15) * 4;

    const int aid0 = tid * 2, aid1 = tid * 2 + 1;
    const int am0 = aid0 >> 2, ak0 = (aid0 & 3) * 4;
    const int am1 = aid1 >> 2, ak1 = (aid1 & 3) * 4;
    const int bk0 = aid0 >> 4, bn0 = (aid0 & 15) * 4;
    const int bk1 = aid1 >> 4, bn1 = (aid1 & 15) * 4;

    ull acc[4][4];
#pragma unroll
    for (int j = 0; j < 4; j++)
#pragma unroll
        for (int i = 0; i < 4; i++) acc[j][i] = 0ull;

    float4 ra0, ra1, rb0, rb1;

#define FETCH(T)                                                                   \
    do {                                                                           \
        int k0 = kbase + (T) * 16;                                                 \
        const float* base; int stride, off;                                        \
        if (k0 < ASR_)        { base = asr; stride = ASR_; off = k0; }             \
        else if (k0 < ZPRE_)  { base = mmv; stride = MM_;  off = k0 - ASR_; }      \
        else                  { base = g_P; stride = F_ * K_; off = k0 - ZPRE_; }  \
        ra0 = *(const float4*)(base + (size_t)(gm + am0) * stride + off + ak0);    \
        ra1 = *(const float4*)(base + (size_t)(gm + am1) * stride + off + ak1);    \
        const float* bb = g_Bmat + (size_t)k0 * OUT_ + gn;                         \
        rb0 = *(const float4*)(bb + (size_t)bk0 * OUT_ + bn0);                     \
        rb1 = *(const float4*)(bb + (size_t)bk1 * OUT_ + bn1);                     \
    } while (0)

#define STASH()                                                                    \
    do {                                                                           \
        As[ak0 + 0][am0] = ra0.x; As[ak0 + 1][am0] = ra0.y;                        \
        As[ak0 + 2][am0] = ra0.z; As[ak0 + 3][am0] = ra0.w;                        \
        As[ak1 + 0][am1] = ra1.x; As[ak1 + 1][am1] = ra1.y;                        \
        As[ak1 + 2][am1] = ra1.z; As[ak1 + 3][am1] = ra1.w;                        \
        *(float4*)&Bs[bk0][bn0] = rb0;                                             \
        *(float4*)&Bs[bk1][bn1] = rb1;                                             \
    } while (0)

    const int T = KHALF / 16;   // 156
    FETCH(0);
    STASH();
    __syncthreads();

    for (int t = 0; t < T; t++) {
        if (t + 1 < T) FETCH(t + 1);
#pragma unroll
        for (int kk = 0; kk < 16; kk++) {
            ull a2[4];
#pragma unroll
            for (int j = 0; j < 4; j++)
                a2[j] = *(const ull*)&As[kk][m0 + 2 * j];
            float4 bv = *(const float4*)&Bs[kk][n0];
            ull bd0 = pack2(bv.x, bv.x), bd1 = pack2(bv.y, bv.y);
            ull bd2 = pack2(bv.z, bv.z), bd3 = pack2(bv.w, bv.w);
#pragma unroll
            for (int j = 0; j < 4; j++) {
                ffma2(acc[j][0], a2[j], bd0);
                ffma2(acc[j][1], a2[j], bd1);
                ffma2(acc[j][2], a2[j], bd2);
                ffma2(acc[j][3], a2[j], bd3);
            }
        }
        __syncthreads();
        if (t + 1 < T) STASH();
        __syncthreads();
    }

    float* outp = g_CP + (size_t)blockIdx.z * (B_ * OUT_);
#pragma unroll
    for (int j = 0; j < 4; j++) {
        const int m = gm + m0 + 2 * j;
#pragma unroll
        for (int i = 0; i < 4; i++) {
            float lo, hi; unpack2(acc[j][i], lo, hi);
            outp[(size_t)m * OUT_ + gn + n0 + i] = lo;
            outp[(size_t)(m + 1) * OUT_ + gn + n0 + i] = hi;
        }
    }
#undef FETCH
#undef STASH
}

// ============================================================
// Kernel D: out = relu(CP[0] + CP[1] + bias)
// grid = 512, 256 threads, float4
// ============================================================
__global__ __launch_bounds__(256) void kernelD(
    const float* __restrict__ pb, float* __restrict__ out)
{
    const int idx = blockIdx.x * 256 + threadIdx.x;   // float4 index, 131072 total
    float4 a = ((const float4*)g_CP)[idx];
    float4 b = ((const float4*)(g_CP + (size_t)B_ * OUT_))[idx];
    float4 bi = ((const float4*)pb)[idx & (OUT_ / 4 - 1)];
    float4 r;
    r.x = fmaxf(a.x + b.x + bi.x, 0.f);
    r.y = fmaxf(a.y + b.y + bi.y, 0.f);
    r.z = fmaxf(a.z + b.z + bi.z, 0.f);
    r.w = fmaxf(a.w + b.w + bi.w, 0.f);
    ((float4*)out)[idx] = r;
}

extern "C" void kernel_launch(void* const* d_in, const int* in_sizes, int n_in,
                              void* d_out, int out_size)
{
    const float* stat = (const float*)d_in[0];
    const float* asr  = (const float*)d_in[1];
    const float* mmv  = (const float*)d_in[2];
    const float* w1   = (const float*)d_in[3];
    const float* b1   = (const float*)d_in[4];
    const float* w2   = (const float*)d_in[5];
    const float* b2   = (const float*)d_in[6];
    const float* tau  = (const float*)d_in[7];
    const float* emb  = (const float*)d_in[8];
    const float* pw   = (const float*)d_in[9];
    const float* pb   = (const float*)d_in[10];
    float* out = (float*)d_out;

    kernelA<<<F_, 256>>>(stat, w1, b1, w2, b2, tau);
    kernelB<<<F_ + ZPRE_ / 32, 256>>>(emb, pw);
    dim3 gc(B_ / 64, OUT_ / 64, 2);
    kernelC<<<gc, 128>>>(asr, mmv);
    kernelD<<<(B_ * OUT_ / 4) / 256, 256>>>(pb, out);
}